// round 2
// baseline (speedup 1.0000x reference)
#include <cuda_runtime.h>

#define N_MAX 50000
#define E_MAX 800000
#define HD 128
#define NH 8
#define DH 16

// ---- scratch (device globals; no allocation allowed) ----
__device__ float g_hf[N_MAX * HD];      // nfeat @ W_fc
__device__ float g_el[N_MAX * NH];
__device__ float g_er[N_MAX * NH];
__device__ int   g_m[N_MAX * NH];       // float bits; init -inf
__device__ float g_denom[N_MAX * NH];
__device__ float g_indeg[N_MAX];
__device__ float g_Sagg[N_MAX * HD];    // segment_sum(efeat)
__device__ float g_he[N_MAX * HD];      // Sagg @ W_e (undivided)
__device__ float g_ex[E_MAX * NH];      // exp(e - m[dst])

// vectorized float4 reduction to global memory (sm_90+)
__device__ __forceinline__ void red_add_v4(float* p, float x, float y, float z, float w) {
    asm volatile("red.global.add.v4.f32 [%0], {%1,%2,%3,%4};"
                 :: "l"(p), "f"(x), "f"(y), "f"(z), "f"(w) : "memory");
}

// ---------------- init (grid-stride over the largest extent) ----------------
__global__ void init_kernel(float* __restrict__ out, int N) {
    int total = N * HD;
    for (int i = blockIdx.x * blockDim.x + threadIdx.x; i < total;
         i += gridDim.x * blockDim.x) {
        out[i] = 0.f;
        g_Sagg[i] = 0.f;
        if (i < N * NH) { g_denom[i] = 0.f; g_m[i] = (int)0xFF800000; }  // -inf
        if (i < N) g_indeg[i] = 0.f;
    }
}

// ---------------- 128x128 GEMM: out[r,c] = sum_k A[r,k]*W[k,c] ----------------
// mode 0: also compute el/er head reductions.  mode 1: plain GEMM.
__global__ void gemm128_kernel(const float* __restrict__ A, const float* __restrict__ W,
                               float* __restrict__ out, int nrows, int mode,
                               const float* __restrict__ attn_l, const float* __restrict__ attn_r) {
    __shared__ float Ws[64 * 128];      // 32 KB (one K-chunk of W)
    __shared__ float As[2][64][20];     // transposed A tiles, stride 20 floats (80 B, 16B-aligned)
    int t = threadIdx.x;
    int col = t & 127;
    int rg = t >> 7;                    // row-group 0/1
    int base = blockIdx.x * 32 + rg * 16;

    float acc[16];
#pragma unroll
    for (int r = 0; r < 16; r++) acc[r] = 0.f;

    for (int kc = 0; kc < 2; kc++) {
        // load W chunk (rows kc*64 .. +63), coalesced
#pragma unroll
        for (int i = 0; i < 32; i++) {
            int idx = i * 256 + t;      // 0..8191
            Ws[idx] = W[kc * 64 * 128 + idx];
        }
        // load A tile [16 rows x 64 k] transposed into As[rg][k][r]
#pragma unroll
        for (int i = 0; i < 8; i++) {
            int lin = i * 128 + col;    // 0..1023
            int r = lin >> 6;
            int k = lin & 63;
            int row = base + r;
            float v = (row < nrows) ? A[row * 128 + kc * 64 + k] : 0.f;
            As[rg][k][r] = v;
        }
        __syncthreads();
#pragma unroll
        for (int k = 0; k < 64; k++) {
            float w = Ws[k * 128 + col];
            const float4* ap = (const float4*)&As[rg][k][0];
            float4 a0 = ap[0], a1 = ap[1], a2 = ap[2], a3 = ap[3];
            acc[0]  += a0.x * w; acc[1]  += a0.y * w; acc[2]  += a0.z * w; acc[3]  += a0.w * w;
            acc[4]  += a1.x * w; acc[5]  += a1.y * w; acc[6]  += a1.z * w; acc[7]  += a1.w * w;
            acc[8]  += a2.x * w; acc[9]  += a2.y * w; acc[10] += a2.z * w; acc[11] += a2.w * w;
            acc[12] += a3.x * w; acc[13] += a3.y * w; acc[14] += a3.z * w; acc[15] += a3.w * w;
        }
        __syncthreads();
    }

    if (mode == 0) {
        float al = attn_l[col];         // attn_l is [8,16] row-major = 128 floats
        float ar = attn_r[col];
        int h = col >> 4;
        int d = col & 15;
#pragma unroll
        for (int r = 0; r < 16; r++) {
            int row = base + r;
            float v = acc[r];
            if (row < nrows) out[row * 128 + col] = v;
            float pl = v * al, pr = v * ar;
#pragma unroll
            for (int off = 8; off > 0; off >>= 1) {
                pl += __shfl_down_sync(0xffffffffu, pl, off, 16);
                pr += __shfl_down_sync(0xffffffffu, pr, off, 16);
            }
            if (d == 0 && row < nrows) {
                g_el[row * NH + h] = pl;
                g_er[row * NH + h] = pr;
            }
        }
    } else {
#pragma unroll
        for (int r = 0; r < 16; r++) {
            int row = base + r;
            if (row < nrows) out[row * 128 + col] = acc[r];
        }
    }
}

// ---------------- edge-feature scatter: Sagg[dst] += efeat[e]; indeg[dst]++ ----------------
__global__ void scatter_edge_feat(const float4* __restrict__ efeat4, const int* __restrict__ dst, int E) {
    int warp = (blockIdx.x * blockDim.x + threadIdx.x) >> 5;
    int lane = threadIdx.x & 31;
    if (warp >= E) return;
    int d = dst[warp];
    float4 v = efeat4[warp * 32 + lane];
    red_add_v4(&g_Sagg[d * 128 + lane * 4], v.x, v.y, v.z, v.w);
    if (lane == 0) atomicAdd(&g_indeg[d], 1.0f);
}

__device__ __forceinline__ float leaky02(float x) { return x > 0.f ? x : 0.2f * x; }

// ---------------- attention pass A: segment max ----------------
// Mixed-sign float max via signed atomicMax (positives) / unsigned atomicMin
// (negatives): both orders converge to true max because positive-float bits
// win signed-max against negative-float bits and win unsigned-min too.
__global__ void attn_max_kernel(const int* __restrict__ src, const int* __restrict__ dst, int E) {
    int e = blockIdx.x * blockDim.x + threadIdx.x;
    if (e >= E) return;
    int s = src[e], d = dst[e];
    const float4* el4 = (const float4*)&g_el[s * NH];
    const float4* er4 = (const float4*)&g_er[d * NH];
    float4 a0 = el4[0], a1 = el4[1], b0 = er4[0], b1 = er4[1];
    float ev[8] = {a0.x + b0.x, a0.y + b0.y, a0.z + b0.z, a0.w + b0.w,
                   a1.x + b1.x, a1.y + b1.y, a1.z + b1.z, a1.w + b1.w};
    int* mbase = &g_m[d * NH];
#pragma unroll
    for (int h = 0; h < 8; h++) {
        float x = leaky02(ev[h]);
        if (x >= 0.f) atomicMax(mbase + h, __float_as_int(x));
        else          atomicMin((unsigned int*)(mbase + h), __float_as_uint(x));
    }
}

// ---------------- attention pass B: ex = exp(e - m[dst]); denom += ex ----------------
__global__ void attn_exp_kernel(const int* __restrict__ src, const int* __restrict__ dst, int E) {
    int e = blockIdx.x * blockDim.x + threadIdx.x;
    if (e >= E) return;
    int s = src[e], d = dst[e];
    const float4* el4 = (const float4*)&g_el[s * NH];
    const float4* er4 = (const float4*)&g_er[d * NH];
    const float4* m4  = (const float4*)&g_m[d * NH];   // bits are float
    float4 a0 = el4[0], a1 = el4[1], b0 = er4[0], b1 = er4[1];
    float4 m0 = m4[0],  m1 = m4[1];
    float x0 = __expf(leaky02(a0.x + b0.x) - m0.x);
    float x1 = __expf(leaky02(a0.y + b0.y) - m0.y);
    float x2 = __expf(leaky02(a0.z + b0.z) - m0.z);
    float x3 = __expf(leaky02(a0.w + b0.w) - m0.w);
    float x4 = __expf(leaky02(a1.x + b1.x) - m1.x);
    float x5 = __expf(leaky02(a1.y + b1.y) - m1.y);
    float x6 = __expf(leaky02(a1.z + b1.z) - m1.z);
    float x7 = __expf(leaky02(a1.w + b1.w) - m1.w);
    float4* ex4 = (float4*)&g_ex[e * NH];
    ex4[0] = make_float4(x0, x1, x2, x3);
    ex4[1] = make_float4(x4, x5, x6, x7);
    red_add_v4(&g_denom[d * NH],     x0, x1, x2, x3);
    red_add_v4(&g_denom[d * NH + 4], x4, x5, x6, x7);
}

// ---------------- attention pass C: out[dst] += (ex/denom[dst]) * hf[src] ----------------
__global__ void agg_scatter_kernel(const int* __restrict__ src, const int* __restrict__ dst,
                                   float* __restrict__ out, int E) {
    int warp = (blockIdx.x * blockDim.x + threadIdx.x) >> 5;
    int lane = threadIdx.x & 31;
    if (warp >= E) return;
    int s = src[warp], d = dst[warp];
    int h = lane >> 2;                              // 4 lanes per head (16 floats/head)
    float a = g_ex[warp * NH + h] / g_denom[d * NH + h];
    float4 v = ((const float4*)g_hf)[s * 32 + lane];
    red_add_v4(&out[d * 128 + lane * 4], a * v.x, a * v.y, a * v.z, a * v.w);
}

// ---------------- finalize: out = agg + bias + hf/(deg+1) + he/max(deg,1) + b_e*(deg>0) ----------------
__global__ void finalize_kernel(float4* __restrict__ out, const float4* __restrict__ bias4,
                                const float4* __restrict__ be4, int N) {
    int i = blockIdx.x * blockDim.x + threadIdx.x;   // over N*32 float4s
    if (i >= N * 32) return;
    int n = i >> 5;
    int c = i & 31;
    float deg = g_indeg[n];
    float inv1 = 1.f / (deg + 1.f);
    float invm = 1.f / fmaxf(deg, 1.f);
    float gate = deg > 0.f ? 1.f : 0.f;
    float4 o  = out[i];
    float4 hv = ((const float4*)g_hf)[i];
    float4 he = ((const float4*)g_he)[i];
    float4 b  = bias4[c];
    float4 be = be4[c];
    o.x += b.x + hv.x * inv1 + he.x * invm + be.x * gate;
    o.y += b.y + hv.y * inv1 + he.y * invm + be.y * gate;
    o.z += b.z + hv.z * inv1 + he.z * invm + be.z * gate;
    o.w += b.w + hv.w * inv1 + he.w * invm + be.w * gate;
    out[i] = o;
}

extern "C" void kernel_launch(void* const* d_in, const int* in_sizes, int n_in,
                              void* d_out, int out_size) {
    const float* nfeat  = (const float*)d_in[0];
    const float* efeat  = (const float*)d_in[1];
    const int*   src    = (const int*)d_in[2];
    const int*   dst    = (const int*)d_in[3];
    const float* W_fc   = (const float*)d_in[4];
    const float* attn_l = (const float*)d_in[5];
    const float* attn_r = (const float*)d_in[6];
    const float* bias   = (const float*)d_in[7];
    const float* W_e    = (const float*)d_in[8];
    const float* b_e    = (const float*)d_in[9];
    float* out = (float*)d_out;

    int N = in_sizes[0] / 128;
    int E = in_sizes[2];

    float* d_hf;   cudaGetSymbolAddress((void**)&d_hf,   g_hf);
    float* d_Sagg; cudaGetSymbolAddress((void**)&d_Sagg, g_Sagg);
    float* d_he;   cudaGetSymbolAddress((void**)&d_he,   g_he);

    init_kernel<<<592, 256>>>(out, N);
    gemm128_kernel<<<(N + 31) / 32, 256>>>(nfeat, W_fc, d_hf, N, 0, attn_l, attn_r);
    scatter_edge_feat<<<(E + 7) / 8, 256>>>((const float4*)efeat, dst, E);
    attn_max_kernel<<<(E + 255) / 256, 256>>>(src, dst, E);
    attn_exp_kernel<<<(E + 255) / 256, 256>>>(src, dst, E);
    agg_scatter_kernel<<<(E + 7) / 8, 256>>>(src, dst, out, E);
    gemm128_kernel<<<(N + 31) / 32, 256>>>(d_Sagg, W_e, d_he, N, 1, nullptr, nullptr);
    finalize_kernel<<<(N * 32 + 255) / 256, 256>>>((float4*)out, (const float4*)bias,
                                                   (const float4*)b_e, N);
}

// round 3
// speedup vs baseline: 1.1350x; 1.1350x over previous
#include <cuda_runtime.h>

#define N_MAX 50000
#define E_MAX 800000
#define HD 128
#define NH 8

// ---- scratch (device globals; no allocation allowed) ----
__device__ float g_hf[N_MAX * HD];      // nfeat @ W_fc
__device__ float g_el[N_MAX * NH];
__device__ float g_er[N_MAX * NH];
__device__ float g_denom[N_MAX * NH];
__device__ float g_indeg[N_MAX];
__device__ float g_Sagg[N_MAX * HD];    // segment_sum(efeat)
__device__ float g_he[N_MAX * HD];      // Sagg @ W_e (undivided)

// vectorized float4 reduction to global memory (sm_90+)
__device__ __forceinline__ void red_add_v4(float* p, float x, float y, float z, float w) {
    asm volatile("red.global.add.v4.f32 [%0], {%1,%2,%3,%4};"
                 :: "l"(p), "f"(x), "f"(y), "f"(z), "f"(w) : "memory");
}
__device__ __forceinline__ void red_add_f32(float* p, float x) {
    asm volatile("red.global.add.f32 [%0], %1;" :: "l"(p), "f"(x) : "memory");
}

// packed f32x2 helpers (FFMA2 — PTX-only path on sm_103a)
__device__ __forceinline__ unsigned long long pack2(float lo, float hi) {
    unsigned long long r;
    asm("mov.b64 %0, {%1, %2};" : "=l"(r) : "r"(__float_as_uint(lo)), "r"(__float_as_uint(hi)));
    return r;
}
__device__ __forceinline__ void fma2(unsigned long long& acc, unsigned long long a, unsigned long long b) {
    asm("fma.rn.f32x2 %0, %1, %2, %0;" : "+l"(acc) : "l"(a), "l"(b));
}
__device__ __forceinline__ void unpack2(unsigned long long v, float& lo, float& hi) {
    unsigned int l, h;
    asm("mov.b64 {%0, %1}, %2;" : "=r"(l), "=r"(h) : "l"(v));
    lo = __uint_as_float(l); hi = __uint_as_float(h);
}

// ---------------- 128x128 GEMM: out[r,c] = sum_k A[r,k]*W[k,c] ----------------
// mode 0: also compute el/er head reductions.  mode 1: plain GEMM.
__global__ void gemm128_kernel(const float* __restrict__ A, const float* __restrict__ W,
                               float* __restrict__ out, int nrows, int mode,
                               const float* __restrict__ attn_l, const float* __restrict__ attn_r) {
    __shared__ float Ws[64 * 128];      // 32 KB (one K-chunk of W)
    __shared__ float As[2][64][20];     // transposed A tiles, stride 20 floats (80 B, 16B-aligned)
    int t = threadIdx.x;
    int col = t & 127;
    int rg = t >> 7;                    // row-group 0/1
    int base = blockIdx.x * 32 + rg * 16;

    unsigned long long acc2[8];         // 16 fp32 accumulators as 8 f32x2 pairs
#pragma unroll
    for (int r = 0; r < 8; r++) acc2[r] = 0ull;

    for (int kc = 0; kc < 2; kc++) {
#pragma unroll
        for (int i = 0; i < 32; i++) {
            int idx = i * 256 + t;      // 0..8191
            Ws[idx] = W[kc * 64 * 128 + idx];
        }
#pragma unroll
        for (int i = 0; i < 8; i++) {
            int lin = i * 128 + col;    // 0..1023
            int r = lin >> 6;
            int k = lin & 63;
            int row = base + r;
            float v = (row < nrows) ? A[row * 128 + kc * 64 + k] : 0.f;
            As[rg][k][r] = v;
        }
        __syncthreads();
#pragma unroll
        for (int k = 0; k < 64; k++) {
            float w = Ws[k * 128 + col];
            unsigned long long ww = pack2(w, w);
            const unsigned long long* ap = (const unsigned long long*)&As[rg][k][0];
#pragma unroll
            for (int p = 0; p < 8; p++) fma2(acc2[p], ap[p], ww);
        }
        __syncthreads();
    }

    float acc[16];
#pragma unroll
    for (int p = 0; p < 8; p++) unpack2(acc2[p], acc[2 * p], acc[2 * p + 1]);

    if (mode == 0) {
        float al = attn_l[col];         // attn_l is [8,16] row-major = 128 floats
        float ar = attn_r[col];
        int h = col >> 4;
        int d = col & 15;
#pragma unroll
        for (int r = 0; r < 16; r++) {
            int row = base + r;
            float v = acc[r];
            if (row < nrows) out[row * 128 + col] = v;
            float pl = v * al, pr = v * ar;
#pragma unroll
            for (int off = 8; off > 0; off >>= 1) {
                pl += __shfl_down_sync(0xffffffffu, pl, off, 16);
                pr += __shfl_down_sync(0xffffffffu, pr, off, 16);
            }
            if (d == 0 && row < nrows) {
                g_el[row * NH + h] = pl;
                g_er[row * NH + h] = pr;
            }
        }
    } else {
#pragma unroll
        for (int r = 0; r < 16; r++) {
            int row = base + r;
            if (row < nrows) out[row * 128 + col] = acc[r];
        }
    }
}

// ---------------- edge-feature scatter: Sagg[dst] += efeat[e]; indeg[dst]++ ----------------
__global__ void scatter_edge_feat(const float4* __restrict__ efeat4, const int* __restrict__ dst, int E) {
    int warp = (blockIdx.x * blockDim.x + threadIdx.x) >> 5;
    int lane = threadIdx.x & 31;
    if (warp >= E) return;
    int d = dst[warp];
    float4 v = efeat4[warp * 32 + lane];
    red_add_v4(&g_Sagg[d * 128 + lane * 4], v.x, v.y, v.z, v.w);
    if (lane == 0) atomicAdd(&g_indeg[d], 1.0f);
}

__device__ __forceinline__ float leaky02(float x) { return x > 0.f ? x : 0.2f * x; }

// ---------------- fused attention aggregate:
// ex = exp(leaky(el[s]+er[d]));  denom[d] += ex;  out[d] += ex * hf[s]
// (division by denom deferred to finalize; softmax is shift-invariant so the
//  segment-max subtraction is dropped — scores are O(1), no overflow risk)
__global__ void agg_fused_kernel(const int* __restrict__ src, const int* __restrict__ dst,
                                 float* __restrict__ out, int E) {
    int warp = (blockIdx.x * blockDim.x + threadIdx.x) >> 5;
    int lane = threadIdx.x & 31;
    if (warp >= E) return;
    int s = src[warp], d = dst[warp];
    int hh = lane & 7;
    float ev = g_el[s * NH + hh] + g_er[d * NH + hh];
    float exv = __expf(leaky02(ev));
    if (lane < 8) red_add_f32(&g_denom[d * NH + hh], exv);
    float a = __shfl_sync(0xffffffffu, exv, lane >> 2);   // head of this lane's 16-col slice
    float4 v = ((const float4*)g_hf)[s * 32 + lane];
    red_add_v4(&out[d * 128 + lane * 4], a * v.x, a * v.y, a * v.z, a * v.w);
}

// ---------------- finalize:
// out = agg_raw/denom + bias + hf/(deg+1) + he/max(deg,1) + b_e*(deg>0)
__global__ void finalize_kernel(float4* __restrict__ out, const float4* __restrict__ bias4,
                                const float4* __restrict__ be4, int N) {
    int i = blockIdx.x * blockDim.x + threadIdx.x;   // over N*32 float4s
    if (i >= N * 32) return;
    int n = i >> 5;
    int c = i & 31;
    int h = c >> 2;
    float den = g_denom[n * NH + h];
    float invden = den > 0.f ? 1.f / den : 0.f;
    float deg = g_indeg[n];
    float inv1 = 1.f / (deg + 1.f);
    float invm = 1.f / fmaxf(deg, 1.f);
    float gate = deg > 0.f ? 1.f : 0.f;
    float4 o  = out[i];
    float4 hv = ((const float4*)g_hf)[i];
    float4 he = ((const float4*)g_he)[i];
    float4 b  = bias4[c];
    float4 be = be4[c];
    o.x = o.x * invden + b.x + hv.x * inv1 + he.x * invm + be.x * gate;
    o.y = o.y * invden + b.y + hv.y * inv1 + he.y * invm + be.y * gate;
    o.z = o.z * invden + b.z + hv.z * inv1 + he.z * invm + be.z * gate;
    o.w = o.w * invden + b.w + hv.w * inv1 + he.w * invm + be.w * gate;
    out[i] = o;
}

extern "C" void kernel_launch(void* const* d_in, const int* in_sizes, int n_in,
                              void* d_out, int out_size) {
    const float* nfeat  = (const float*)d_in[0];
    const float* efeat  = (const float*)d_in[1];
    const int*   src    = (const int*)d_in[2];
    const int*   dst    = (const int*)d_in[3];
    const float* W_fc   = (const float*)d_in[4];
    const float* attn_l = (const float*)d_in[5];
    const float* attn_r = (const float*)d_in[6];
    const float* bias   = (const float*)d_in[7];
    const float* W_e    = (const float*)d_in[8];
    const float* b_e    = (const float*)d_in[9];
    float* out = (float*)d_out;

    int N = in_sizes[0] / 128;
    int E = in_sizes[2];

    float* d_hf;    cudaGetSymbolAddress((void**)&d_hf,    g_hf);
    float* d_Sagg;  cudaGetSymbolAddress((void**)&d_Sagg,  g_Sagg);
    float* d_he;    cudaGetSymbolAddress((void**)&d_he,    g_he);
    float* d_denom; cudaGetSymbolAddress((void**)&d_denom, g_denom);
    float* d_indeg; cudaGetSymbolAddress((void**)&d_indeg, g_indeg);

    cudaMemsetAsync(out,     0, (size_t)N * HD * sizeof(float));
    cudaMemsetAsync(d_Sagg,  0, (size_t)N * HD * sizeof(float));
    cudaMemsetAsync(d_denom, 0, (size_t)N * NH * sizeof(float));
    cudaMemsetAsync(d_indeg, 0, (size_t)N * sizeof(float));

    gemm128_kernel<<<(N + 31) / 32, 256>>>(nfeat, W_fc, d_hf, N, 0, attn_l, attn_r);
    scatter_edge_feat<<<(E + 7) / 8, 256>>>((const float4*)efeat, dst, E);
    agg_fused_kernel<<<(E + 7) / 8, 256>>>(src, dst, out, E);
    gemm128_kernel<<<(N + 31) / 32, 256>>>(d_Sagg, W_e, d_he, N, 1, nullptr, nullptr);
    finalize_kernel<<<(N * 32 + 255) / 256, 256>>>((float4*)out, (const float4*)bias,
                                                   (const float4*)b_e, N);
}

// round 6
// speedup vs baseline: 1.3858x; 1.2210x over previous
#include <cuda_runtime.h>

#define N_MAX 50000
#define E_MAX 800000
#define HD 128
#define NH 8

// ---- scratch (device globals; no allocation allowed) ----
__device__ float g_hf[N_MAX * HD];      // nfeat @ W_fc
__device__ float g_el[N_MAX * NH];
__device__ float g_er[N_MAX * NH];
__device__ float g_denom[N_MAX * NH];
__device__ float g_indeg[N_MAX];
__device__ float g_Sagg[N_MAX * HD];    // segment_sum(efeat)
__device__ float g_he[N_MAX * HD];      // Sagg @ W_e (undivided)

// vectorized float4 reduction to global memory (sm_90+)
__device__ __forceinline__ void red_add_v4(float* p, float x, float y, float z, float w) {
    asm volatile("red.global.add.v4.f32 [%0], {%1,%2,%3,%4};"
                 :: "l"(p), "f"(x), "f"(y), "f"(z), "f"(w) : "memory");
}
__device__ __forceinline__ void red_add_f32(float* p, float x) {
    asm volatile("red.global.add.f32 [%0], %1;" :: "l"(p), "f"(x) : "memory");
}

// packed f32x2 helpers (FFMA2 — PTX-only path on sm_103a)
__device__ __forceinline__ unsigned long long pack2(float lo, float hi) {
    unsigned long long r;
    asm("mov.b64 %0, {%1, %2};" : "=l"(r) : "r"(__float_as_uint(lo)), "r"(__float_as_uint(hi)));
    return r;
}
__device__ __forceinline__ void fma2(unsigned long long& acc, unsigned long long a, unsigned long long b) {
    asm("fma.rn.f32x2 %0, %1, %2, %0;" : "+l"(acc) : "l"(a), "l"(b));
}
__device__ __forceinline__ void unpack2(unsigned long long v, float& lo, float& hi) {
    unsigned int l, h;
    asm("mov.b64 {%0, %1}, %2;" : "=r"(l), "=r"(h) : "l"(v));
    lo = __uint_as_float(l); hi = __uint_as_float(h);
}

// ---------------- GEMM: out[r,c] = sum_k A[r,k]*W[k,c], 128x128 tile, 8x8/thread ----
// mode 0: also compute el/er head reductions.  mode 1: plain GEMM.
#define KC 32
__global__ __launch_bounds__(256, 2)
void gemm_kernel(const float* __restrict__ A, const float* __restrict__ W,
                 float* __restrict__ out, int nrows, int mode,
                 const float* __restrict__ attn_l, const float* __restrict__ attn_r) {
    __shared__ float Ws[KC][128];       // 16 KB
    __shared__ float As[128][KC + 4];   // 18 KB, row stride 36 floats (144 B, 16B-aligned)
    int t = threadIdx.x;
    int tx = t & 15;                    // col group -> cols 8*tx .. 8*tx+7
    int ty = t >> 4;                    // row group -> rows 8*ty .. 8*ty+7
    int rbase = blockIdx.x * 128;

    unsigned long long acc[8][4];       // 8 rows x 4 col-pairs
#pragma unroll
    for (int i = 0; i < 8; i++)
#pragma unroll
        for (int j = 0; j < 4; j++) acc[i][j] = 0ull;

    for (int kc = 0; kc < 4; kc++) {
        // Ws chunk: 32x128 floats, 4 float4 per thread, coalesced
#pragma unroll
        for (int i = 0; i < 4; i++) {
            int lin = i * 256 + t;
            int r = lin >> 5, c4 = lin & 31;
            *((float4*)&Ws[r][c4 * 4]) = ((const float4*)W)[(kc * 32 + r) * 32 + c4];
        }
        // As chunk: 128 rows x 32 k, 4 float4 per thread, coalesced
#pragma unroll
        for (int i = 0; i < 4; i++) {
            int lin = i * 256 + t;
            int r = lin >> 3, k4 = lin & 7;
            int row = rbase + r;
            float4 v = (row < nrows) ? ((const float4*)A)[(size_t)row * 32 + kc * 8 + k4]
                                     : make_float4(0.f, 0.f, 0.f, 0.f);
            *((float4*)&As[r][k4 * 4]) = v;
        }
        __syncthreads();
#pragma unroll
        for (int k = 0; k < KC; k++) {
            unsigned long long w2[4];   // 8 W cols as 4 adjacent pairs (LDS.64, no pack)
#pragma unroll
            for (int j = 0; j < 4; j++)
                w2[j] = *(const unsigned long long*)&Ws[k][tx * 8 + j * 2];
#pragma unroll
            for (int i = 0; i < 8; i++) {
                float a = As[ty * 8 + i][k];          // broadcast within half-warp
                unsigned long long aa = pack2(a, a);
#pragma unroll
                for (int j = 0; j < 4; j++) fma2(acc[i][j], aa, w2[j]);
            }
        }
        __syncthreads();
    }

    float al[8], ar[8];
    if (mode == 0) {
#pragma unroll
        for (int j = 0; j < 8; j++) { al[j] = attn_l[tx * 8 + j]; ar[j] = attn_r[tx * 8 + j]; }
    }

#pragma unroll
    for (int i = 0; i < 8; i++) {
        int row = rbase + ty * 8 + i;
        float c[8];
#pragma unroll
        for (int j = 0; j < 4; j++) unpack2(acc[i][j], c[2 * j], c[2 * j + 1]);
        if (row < nrows) {
            *(float4*)&out[(size_t)row * 128 + tx * 8]     = make_float4(c[0], c[1], c[2], c[3]);
            *(float4*)&out[(size_t)row * 128 + tx * 8 + 4] = make_float4(c[4], c[5], c[6], c[7]);
        }
        if (mode == 0) {
            float pl = 0.f, pr = 0.f;
#pragma unroll
            for (int j = 0; j < 8; j++) { pl += c[j] * al[j]; pr += c[j] * ar[j]; }
            // partner lane (tx^1) holds the other half of this head's 16 cols
            pl += __shfl_xor_sync(0xffffffffu, pl, 1);
            pr += __shfl_xor_sync(0xffffffffu, pr, 1);
            if ((tx & 1) == 0 && row < nrows) {
                g_el[row * NH + (tx >> 1)] = pl;
                g_er[row * NH + (tx >> 1)] = pr;
            }
        }
    }
}

__device__ __forceinline__ float leaky02(float x) { return x > 0.f ? x : 0.2f * x; }

// ---------------- merged edge pass (4 edges per warp):
//   Sagg[dst] += efeat[e];  indeg[dst]++          (econv sum + degree)
//   ex = exp(leaky(el[src]+er[dst])); denom[dst] += ex; out[dst] += ex*hf[src]
// (softmax max-shift dropped: scores are O(1); division deferred to finalize)
__global__ void edge_kernel(const float4* __restrict__ efeat4,
                            const int* __restrict__ src, const int* __restrict__ dst,
                            float* __restrict__ out, int E) {
    int w = (blockIdx.x * blockDim.x + threadIdx.x) >> 5;
    int lane = threadIdx.x & 31;
    int e0 = w * 4;
    if (e0 >= E) return;
    int ne = E - e0; if (ne > 4) ne = 4;

    int sE[4], dE[4];
#pragma unroll
    for (int q = 0; q < 4; q++) {
        int e = e0 + (q < ne ? q : ne - 1);
        sE[q] = src[e]; dE[q] = dst[e];
    }
    // issue all gathers up front (MLP ~ 8 x 16B per lane)
    float4 ef[4], hv[4];
#pragma unroll
    for (int q = 0; q < 4; q++)
        ef[q] = efeat4[(size_t)(e0 + (q < ne ? q : ne - 1)) * 32 + lane];
#pragma unroll
    for (int q = 0; q < 4; q++)
        hv[q] = ((const float4*)g_hf)[(size_t)sE[q] * 32 + lane];

    int hh = lane & 7;
    float exv[4];
#pragma unroll
    for (int q = 0; q < 4; q++) {
        float ev = g_el[sE[q] * NH + hh] + g_er[dE[q] * NH + hh];
        exv[q] = __expf(leaky02(ev));
    }

#pragma unroll
    for (int q = 0; q < 4; q++) {
        if (q < ne) {
            red_add_v4(&g_Sagg[(size_t)dE[q] * 128 + lane * 4],
                       ef[q].x, ef[q].y, ef[q].z, ef[q].w);
            if (lane < 8) red_add_f32(&g_denom[dE[q] * NH + hh], exv[q]);
            if (lane == 0) red_add_f32(&g_indeg[dE[q]], 1.0f);
            float a = __shfl_sync(0xffffffffu, exv[q], lane >> 2);
            red_add_v4(&out[(size_t)dE[q] * 128 + lane * 4],
                       a * hv[q].x, a * hv[q].y, a * hv[q].z, a * hv[q].w);
        }
    }
}

// ---------------- finalize:
// out = agg_raw/denom + bias + hf/(deg+1) + he/max(deg,1) + b_e*(deg>0)
__global__ void finalize_kernel(float4* __restrict__ out, const float4* __restrict__ bias4,
                                const float4* __restrict__ be4, int N) {
    int i = blockIdx.x * blockDim.x + threadIdx.x;   // over N*32 float4s
    if (i >= N * 32) return;
    int n = i >> 5;
    int c = i & 31;
    int h = c >> 2;
    float den = g_denom[n * NH + h];
    float invden = den > 0.f ? 1.f / den : 0.f;
    float deg = g_indeg[n];
    float inv1 = 1.f / (deg + 1.f);
    float invm = 1.f / fmaxf(deg, 1.f);
    float gate = deg > 0.f ? 1.f : 0.f;
    float4 o  = out[i];
    float4 hv = ((const float4*)g_hf)[i];
    float4 he = ((const float4*)g_he)[i];
    float4 b  = bias4[c];
    float4 be = be4[c];
    o.x = o.x * invden + b.x + hv.x * inv1 + he.x * invm + be.x * gate;
    o.y = o.y * invden + b.y + hv.y * inv1 + he.y * invm + be.y * gate;
    o.z = o.z * invden + b.z + hv.z * inv1 + he.z * invm + be.z * gate;
    o.w = o.w * invden + b.w + hv.w * inv1 + he.w * invm + be.w * gate;
    out[i] = o;
}

extern "C" void kernel_launch(void* const* d_in, const int* in_sizes, int n_in,
                              void* d_out, int out_size) {
    const float* nfeat  = (const float*)d_in[0];
    const float* efeat  = (const float*)d_in[1];
    const int*   src    = (const int*)d_in[2];
    const int*   dst    = (const int*)d_in[3];
    const float* W_fc   = (const float*)d_in[4];
    const float* attn_l = (const float*)d_in[5];
    const float* attn_r = (const float*)d_in[6];
    const float* bias   = (const float*)d_in[7];
    const float* W_e    = (const float*)d_in[8];
    const float* b_e    = (const float*)d_in[9];
    float* out = (float*)d_out;

    int N = in_sizes[0] / 128;
    int E = in_sizes[2];

    float* d_hf;    cudaGetSymbolAddress((void**)&d_hf,    g_hf);
    float* d_Sagg;  cudaGetSymbolAddress((void**)&d_Sagg,  g_Sagg);
    float* d_he;    cudaGetSymbolAddress((void**)&d_he,    g_he);
    float* d_denom; cudaGetSymbolAddress((void**)&d_denom, g_denom);
    float* d_indeg; cudaGetSymbolAddress((void**)&d_indeg, g_indeg);

    cudaMemsetAsync(out,     0, (size_t)N * HD * sizeof(float));
    cudaMemsetAsync(d_Sagg,  0, (size_t)N * HD * sizeof(float));
    cudaMemsetAsync(d_denom, 0, (size_t)N * NH * sizeof(float));
    cudaMemsetAsync(d_indeg, 0, (size_t)N * sizeof(float));

    gemm_kernel<<<(N + 127) / 128, 256>>>(nfeat, W_fc, d_hf, N, 0, attn_l, attn_r);

    int warps = (E + 3) / 4;
    edge_kernel<<<(warps * 32 + 255) / 256, 256>>>((const float4*)efeat, src, dst, out, E);

    gemm_kernel<<<(N + 127) / 128, 256>>>(d_Sagg, W_e, d_he, N, 1, nullptr, nullptr);

    finalize_kernel<<<(N * 32 + 255) / 256, 256>>>((float4*)out, (const float4*)bias,
                                                   (const float4*)b_e, N);
}